// round 2
// baseline (speedup 1.0000x reference)
#include <cuda_runtime.h>
#include <math.h>

#define L_   12
#define S_   512
#define B_   4
#define DIN_ 768
#define D_   1024
#define H_   16
#define F_   4096
#define HD_  64
#define T_   (S_*B_)   // 2048 tokens

// ---------------- scratch (static device globals; no runtime allocation) ----
__device__ float g_h[T_*D_];
__device__ float g_q[T_*D_];
__device__ float g_k[T_*D_];
__device__ float g_v[T_*D_];
__device__ float g_attn[T_*D_];
__device__ float g_ff[(size_t)T_*F_];
__device__ float g_scores[(size_t)B_*H_*S_*S_];   // 67 MB

// ---------------- generic fp32 GEMM: C = A[MxK] @ W[KxN] + epilogue --------
// epilogue: + bias[c] + bias2[c] + rowvec[r]*colvec[c]; optional exact GELU;
//           + residual[r,c]
#define BM 128
#define BN 128
#define BKK 8

__global__ __launch_bounds__(256) void gemm_kernel(
    const float* __restrict__ A, const float* __restrict__ Bw,
    const float* __restrict__ bias, const float* __restrict__ bias2,
    const float* __restrict__ rowvec, const float* __restrict__ colvec,
    const float* __restrict__ residual,
    float* __restrict__ C, int M, int N, int K, int gelu_flag)
{
    __shared__ float As[BKK][BM + 4];
    __shared__ float Bs[BKK][BN];

    const int tid = threadIdx.x;
    const int row0 = blockIdx.y * BM;
    const int col0 = blockIdx.x * BN;
    const int ty = tid >> 4, tx = tid & 15;

    float acc[8][8];
    #pragma unroll
    for (int i = 0; i < 8; i++)
        #pragma unroll
        for (int j = 0; j < 8; j++) acc[i][j] = 0.f;

    const int ar = tid >> 1;            // 0..127
    const int ac = (tid & 1) * 4;       // 0 or 4
    const int br = tid >> 5;            // 0..7
    const int bc = (tid & 31) * 4;      // 0..124

    const float* Aptr = A + (size_t)(row0 + ar) * K + ac;
    const float* Bptr = Bw + (size_t)br * N + col0 + bc;

    for (int k0 = 0; k0 < K; k0 += BKK) {
        float4 a = *(const float4*)(Aptr + k0);
        As[ac+0][ar] = a.x; As[ac+1][ar] = a.y;
        As[ac+2][ar] = a.z; As[ac+3][ar] = a.w;
        float4 b = *(const float4*)(Bptr + (size_t)k0 * N);
        *(float4*)&Bs[br][bc] = b;
        __syncthreads();

        #pragma unroll
        for (int k = 0; k < BKK; k++) {
            float av[8], bv[8];
            #pragma unroll
            for (int i = 0; i < 8; i++) av[i] = As[k][ty*8 + i];
            #pragma unroll
            for (int j = 0; j < 8; j++) bv[j] = Bs[k][tx*8 + j];
            #pragma unroll
            for (int i = 0; i < 8; i++)
                #pragma unroll
                for (int j = 0; j < 8; j++)
                    acc[i][j] = fmaf(av[i], bv[j], acc[i][j]);
        }
        __syncthreads();
    }

    #pragma unroll
    for (int i = 0; i < 8; i++) {
        const int r = row0 + ty*8 + i;
        const float rv = rowvec ? rowvec[r] : 0.f;
        #pragma unroll
        for (int j = 0; j < 8; j++) {
            const int c = col0 + tx*8 + j;
            float v = acc[i][j];
            if (bias)   v += bias[c];
            if (bias2)  v += bias2[c];
            if (rowvec) v += rv * colvec[c];
            if (gelu_flag) v = 0.5f * v * (1.f + erff(v * 0.70710678118654752f));
            if (residual) v += residual[(size_t)r * N + c];
            C[(size_t)r * N + c] = v;
        }
    }
}

// ---------------- LayerNorm: one block per token ---------------------------
__global__ __launch_bounds__(256) void ln_kernel(
    const float* __restrict__ x, const float* __restrict__ g,
    const float* __restrict__ bta, float* __restrict__ out)
{
    const int t = blockIdx.x;
    const int tid = threadIdx.x;
    const float* xr = x + (size_t)t * D_;

    float v[4];
    float s = 0.f, s2 = 0.f;
    #pragma unroll
    for (int i = 0; i < 4; i++) {
        v[i] = xr[tid + i*256];
        s  += v[i];
        s2 += v[i] * v[i];
    }
    #pragma unroll
    for (int o = 16; o; o >>= 1) {
        s  += __shfl_xor_sync(0xffffffffu, s,  o);
        s2 += __shfl_xor_sync(0xffffffffu, s2, o);
    }
    __shared__ float ss[8], ss2[8];
    if ((tid & 31) == 0) { ss[tid >> 5] = s; ss2[tid >> 5] = s2; }
    __syncthreads();
    s = 0.f; s2 = 0.f;
    #pragma unroll
    for (int w = 0; w < 8; w++) { s += ss[w]; s2 += ss2[w]; }

    const float mean = s * (1.f / D_);
    const float var  = s2 * (1.f / D_) - mean * mean;
    const float inv  = rsqrtf(var + 1e-5f);

    float* orow = out + (size_t)t * D_;
    #pragma unroll
    for (int i = 0; i < 4; i++) {
        const int c = tid + i*256;
        orow[c] = (v[i] - mean) * inv * g[c] + bta[c];
    }
}

// ---------------- RoPE (in-place, one thread owns the rotation pair) -------
__global__ __launch_bounds__(256) void rope_kernel(float* __restrict__ x)
{
    const int idx = blockIdx.x * 256 + threadIdx.x;   // T_*H_*32 = 1,048,576
    const int j = idx & 31;
    const int h = (idx >> 5) & 15;
    const int t = idx >> 9;                            // token 0..2047
    const int s = t >> 2;                              // sequence position (/B_)

    const float inv_freq = powf(10000.f, -((float)(2*j)) * (1.f / HD_));
    float sn, c;
    sincosf((float)s * inv_freq, &sn, &c);

    float* base = x + (size_t)t * D_ + h * HD_;
    const float x1 = base[j];
    const float x2 = base[j + 32];
    base[j]      = x1 * c - x2 * sn;
    base[j + 32] = x2 * c + x1 * sn;
}

// ---------------- scores = scale * Q K^T, masked ---------------------------
// grid (S/64, S/64, B*H), block 256; per-thread 4x4 output
__global__ __launch_bounds__(256) void qk_kernel(
    const float* __restrict__ q, const float* __restrict__ k,
    const int* __restrict__ mask, float* __restrict__ scores)
{
    const int bh = blockIdx.z;
    const int b = bh >> 4;
    const int h = bh & 15;
    const int qt = blockIdx.y * 64;
    const int kt = blockIdx.x * 64;

    __shared__ float Qs[HD_][65];
    __shared__ float Ks[HD_][65];

    const int tid = threadIdx.x;
    const int ty = tid >> 4, tx = tid & 15;
    const int lr = tid >> 4;
    const int lc = (tid & 15) * 4;

    #pragma unroll
    for (int it = 0; it < 4; it++) {
        const int m = lr + it*16;
        float4 a = *(const float4*)(q + ((size_t)(qt + m) * B_ + b) * D_ + h*HD_ + lc);
        Qs[lc+0][m]=a.x; Qs[lc+1][m]=a.y; Qs[lc+2][m]=a.z; Qs[lc+3][m]=a.w;
        float4 bb = *(const float4*)(k + ((size_t)(kt + m) * B_ + b) * D_ + h*HD_ + lc);
        Ks[lc+0][m]=bb.x; Ks[lc+1][m]=bb.y; Ks[lc+2][m]=bb.z; Ks[lc+3][m]=bb.w;
    }
    __syncthreads();

    float acc[4][4];
    #pragma unroll
    for (int i = 0; i < 4; i++)
        #pragma unroll
        for (int j = 0; j < 4; j++) acc[i][j] = 0.f;

    #pragma unroll
    for (int kk = 0; kk < HD_; kk++) {
        float av[4], bv[4];
        #pragma unroll
        for (int i = 0; i < 4; i++) av[i] = Qs[kk][ty*4 + i];
        #pragma unroll
        for (int j = 0; j < 4; j++) bv[j] = Ks[kk][tx*4 + j];
        #pragma unroll
        for (int i = 0; i < 4; i++)
            #pragma unroll
            for (int j = 0; j < 4; j++)
                acc[i][j] = fmaf(av[i], bv[j], acc[i][j]);
    }

    const float scale = 0.125f;  // 1/sqrt(64)
    #pragma unroll
    for (int i = 0; i < 4; i++) {
        const int qpos = qt + ty*4 + i;
        float* out = scores + ((size_t)bh * S_ + qpos) * S_;
        #pragma unroll
        for (int j = 0; j < 4; j++) {
            const int kpos = kt + tx*4 + j;
            float vsc = acc[i][j] * scale;
            if (mask[b * S_ + kpos] != 0) vsc = -1e30f;
            out[kpos] = vsc;
        }
    }
}

// ---------------- row softmax over 512 keys --------------------------------
__global__ __launch_bounds__(128) void softmax_kernel(float* __restrict__ scores)
{
    const size_t row = blockIdx.x;
    float* p = scores + row * S_;
    const int tid = threadIdx.x;

    float vals[4];
    float m = -3.0e38f;
    #pragma unroll
    for (int i = 0; i < 4; i++) { vals[i] = p[tid + i*128]; m = fmaxf(m, vals[i]); }
    #pragma unroll
    for (int o = 16; o; o >>= 1) m = fmaxf(m, __shfl_xor_sync(0xffffffffu, m, o));
    __shared__ float sm[4], ssum[4];
    if ((tid & 31) == 0) sm[tid >> 5] = m;
    __syncthreads();
    m = fmaxf(fmaxf(sm[0], sm[1]), fmaxf(sm[2], sm[3]));

    float s = 0.f;
    #pragma unroll
    for (int i = 0; i < 4; i++) { vals[i] = __expf(vals[i] - m); s += vals[i]; }
    #pragma unroll
    for (int o = 16; o; o >>= 1) s += __shfl_xor_sync(0xffffffffu, s, o);
    if ((tid & 31) == 0) ssum[tid >> 5] = s;
    __syncthreads();
    const float inv = 1.f / (ssum[0] + ssum[1] + ssum[2] + ssum[3]);

    #pragma unroll
    for (int i = 0; i < 4; i++) p[tid + i*128] = vals[i] * inv;
}

// ---------------- attn = probs @ V, scattered to [t, d] layout -------------
// grid (1, S/64, B*H), block 256
__global__ __launch_bounds__(256) void pv_kernel(
    const float* __restrict__ scores, const float* __restrict__ v,
    float* __restrict__ attn)
{
    const int bh = blockIdx.z;
    const int b = bh >> 4, h = bh & 15;
    const int qt = blockIdx.y * 64;

    __shared__ float Ps[32][65];
    __shared__ float Vs[32][64];

    const int tid = threadIdx.x;
    const int ty = tid >> 4, tx = tid & 15;
    const int pr = tid >> 3;           // 0..31
    const int pc = (tid & 7) * 4;      // 0..28
    const int vr = tid >> 4;           // 0..15
    const int vc = (tid & 15) * 4;     // 0..60

    float acc[4][4];
    #pragma unroll
    for (int i = 0; i < 4; i++)
        #pragma unroll
        for (int j = 0; j < 4; j++) acc[i][j] = 0.f;

    for (int kt = 0; kt < S_; kt += 32) {
        #pragma unroll
        for (int it = 0; it < 2; it++) {
            const int m = pr + it*32;   // q row 0..63
            float4 a = *(const float4*)(scores + ((size_t)bh*S_ + qt + m)*S_ + kt + pc);
            Ps[pc+0][m]=a.x; Ps[pc+1][m]=a.y; Ps[pc+2][m]=a.z; Ps[pc+3][m]=a.w;
        }
        #pragma unroll
        for (int it = 0; it < 2; it++) {
            const int kr = vr + it*16;  // k row 0..31
            float4 bb = *(const float4*)(v + ((size_t)(kt + kr)*B_ + b)*D_ + h*HD_ + vc);
            *(float4*)&Vs[kr][vc] = bb;
        }
        __syncthreads();

        #pragma unroll
        for (int kk = 0; kk < 32; kk++) {
            float av[4], bv[4];
            #pragma unroll
            for (int i = 0; i < 4; i++) av[i] = Ps[kk][ty*4 + i];
            #pragma unroll
            for (int j = 0; j < 4; j++) bv[j] = Vs[kk][tx*4 + j];
            #pragma unroll
            for (int i = 0; i < 4; i++)
                #pragma unroll
                for (int j = 0; j < 4; j++)
                    acc[i][j] = fmaf(av[i], bv[j], acc[i][j]);
        }
        __syncthreads();
    }

    #pragma unroll
    for (int i = 0; i < 4; i++) {
        const int qpos = qt + ty*4 + i;
        float* orow = attn + ((size_t)qpos * B_ + b) * D_ + h*HD_;
        #pragma unroll
        for (int j = 0; j < 4; j++)
            orow[tx*4 + j] = acc[i][j];
    }
}

// ---------------- host orchestration ---------------------------------------
extern "C" void kernel_launch(void* const* d_in, const int* in_sizes, int n_in,
                              void* d_out, int out_size)
{
    (void)in_sizes; (void)n_in; (void)out_size;

    const float* segments  = (const float*)d_in[0];
    const float* durations = (const float*)d_in[1];
    const int*   padmask   = (const int*)d_in[2];   // bool promoted to int32 by harness
    const float* Wproj = (const float*)d_in[3];
    const float* bproj = (const float*)d_in[4];
    const float* Wdur  = (const float*)d_in[5];
    const float* bdur  = (const float*)d_in[6];
    const float* ln1_g = (const float*)d_in[7];
    const float* ln1_b = (const float*)d_in[8];
    const float* Wq = (const float*)d_in[9];
    const float* bq = (const float*)d_in[10];
    const float* Wk = (const float*)d_in[11];
    const float* bk = (const float*)d_in[12];
    const float* Wv = (const float*)d_in[13];
    const float* bv = (const float*)d_in[14];
    const float* Wo = (const float*)d_in[15];
    const float* bo = (const float*)d_in[16];
    const float* ln2_g = (const float*)d_in[17];
    const float* ln2_b = (const float*)d_in[18];
    const float* Wff1 = (const float*)d_in[19];
    const float* bff1 = (const float*)d_in[20];
    const float* Wff2 = (const float*)d_in[21];
    const float* bff2 = (const float*)d_in[22];

    float* x = (float*)d_out;   // residual stream lives in d_out

    float *h, *q, *k, *v, *attn, *ff, *scores;
    cudaGetSymbolAddress((void**)&h,      g_h);
    cudaGetSymbolAddress((void**)&q,      g_q);
    cudaGetSymbolAddress((void**)&k,      g_k);
    cudaGetSymbolAddress((void**)&v,      g_v);
    cudaGetSymbolAddress((void**)&attn,   g_attn);
    cudaGetSymbolAddress((void**)&ff,     g_ff);
    cudaGetSymbolAddress((void**)&scores, g_scores);

    const dim3 blk(256);

    // x = segments @ Wproj + bproj + durations*Wdur + bdur
    gemm_kernel<<<dim3(D_/BN, T_/BM), blk>>>(
        segments, Wproj, bproj, bdur, durations, Wdur, nullptr,
        x, T_, D_, DIN_, 0);

    for (int l = 0; l < L_; l++) {
        const float* wq = Wq + (size_t)l*D_*D_;
        const float* wk = Wk + (size_t)l*D_*D_;
        const float* wv = Wv + (size_t)l*D_*D_;
        const float* wo = Wo + (size_t)l*D_*D_;
        const float* w1 = Wff1 + (size_t)l*D_*F_;
        const float* w2 = Wff2 + (size_t)l*F_*D_;

        ln_kernel<<<T_, 256>>>(x, ln1_g + l*D_, ln1_b + l*D_, h);

        gemm_kernel<<<dim3(D_/BN, T_/BM), blk>>>(h, wq, bq + l*D_,
            nullptr, nullptr, nullptr, nullptr, q, T_, D_, D_, 0);
        gemm_kernel<<<dim3(D_/BN, T_/BM), blk>>>(h, wk, bk + l*D_,
            nullptr, nullptr, nullptr, nullptr, k, T_, D_, D_, 0);
        gemm_kernel<<<dim3(D_/BN, T_/BM), blk>>>(h, wv, bv + l*D_,
            nullptr, nullptr, nullptr, nullptr, v, T_, D_, D_, 0);

        rope_kernel<<<(T_*H_*32)/256, 256>>>(q);
        rope_kernel<<<(T_*H_*32)/256, 256>>>(k);

        qk_kernel<<<dim3(S_/64, S_/64, B_*H_), blk>>>(q, k, padmask, scores);
        softmax_kernel<<<B_*H_*S_, 128>>>(scores);
        pv_kernel<<<dim3(1, S_/64, B_*H_), blk>>>(scores, v, attn);

        // x = x + attn @ Wo + bo
        gemm_kernel<<<dim3(D_/BN, T_/BM), blk>>>(attn, wo, bo + l*D_,
            nullptr, nullptr, nullptr, x, x, T_, D_, D_, 0);

        ln_kernel<<<T_, 256>>>(x, ln2_g + l*D_, ln2_b + l*D_, h);

        // ff = gelu(h @ W1 + b1)
        gemm_kernel<<<dim3(F_/BN, T_/BM), blk>>>(h, w1, bff1 + l*F_,
            nullptr, nullptr, nullptr, nullptr, ff, T_, F_, D_, 1);

        // x = x + ff @ W2 + b2
        gemm_kernel<<<dim3(D_/BN, T_/BM), blk>>>(ff, w2, bff2 + l*D_,
            nullptr, nullptr, nullptr, x, x, T_, D_, F_, 0);
    }
}

// round 3
// speedup vs baseline: 1.4818x; 1.4818x over previous
#include <cuda_runtime.h>
#include <math.h>

#define L_   12
#define S_   512
#define B_   4
#define DIN_ 768
#define D_   1024
#define H_   16
#define F_   4096
#define HD_  64
#define T_   (S_*B_)   // 2048 tokens

// ---------------- scratch (static device globals; no runtime allocation) ----
__device__ float g_h[T_*D_];
__device__ float g_q[T_*D_];
__device__ float g_k[T_*D_];
__device__ float g_v[T_*D_];
__device__ float g_attn[T_*D_];
__device__ float g_ff[(size_t)T_*F_];
__device__ float g_scores[(size_t)B_*H_*S_*S_];   // 67 MB

// ---------------- tf32 helpers ---------------------------------------------
__device__ __forceinline__ unsigned f2tf32(float f) {
    unsigned u;
    asm("cvt.rna.tf32.f32 %0, %1;" : "=r"(u) : "f"(f));
    return u;
}

__device__ __forceinline__ void mma_tf32(float c[4],
    unsigned a0, unsigned a1, unsigned a2, unsigned a3,
    unsigned b0, unsigned b1)
{
    asm volatile(
        "mma.sync.aligned.m16n8k8.row.col.f32.tf32.tf32.f32 "
        "{%0,%1,%2,%3}, {%4,%5,%6,%7}, {%8,%9}, {%0,%1,%2,%3};"
        : "+f"(c[0]), "+f"(c[1]), "+f"(c[2]), "+f"(c[3])
        : "r"(a0), "r"(a1), "r"(a2), "r"(a3), "r"(b0), "r"(b1));
}

// ---------------- tensor-core GEMM (3xTF32): C = A[MxK] @ W[KxN] + epilogue
// epilogue: + bias[c] + bias2[c] + rowvec[r]*colvec[c]; optional exact GELU;
//           + residual[r,c]
// block tile 128x128x32, 8 warps (2x4), warp tile 64x32, m16n8k8
#define TBM 128
#define TBN 128
#define TBK 32
#define PADA 4
#define PADB 8

__global__ __launch_bounds__(256, 1) void gemm_tc(
    const float* __restrict__ A, const float* __restrict__ Bw,
    const float* __restrict__ bias, const float* __restrict__ bias2,
    const float* __restrict__ rowvec, const float* __restrict__ colvec,
    const float* __restrict__ residual,
    float* __restrict__ C, int M, int N, int K, int gelu_flag)
{
    __shared__ float As[TBM][TBK + PADA];   // [m][k]
    __shared__ float Bs[TBK][TBN + PADB];   // [k][n]

    const int tid  = threadIdx.x;
    const int warp = tid >> 5;
    const int lane = tid & 31;
    const int g    = lane >> 2;      // 0..7
    const int tig  = lane & 3;       // 0..3
    const int wm   = (warp >> 2) * 64;   // 0 or 64
    const int wn   = (warp & 3) * 32;    // 0,32,64,96

    const int row0 = blockIdx.y * TBM;
    const int col0 = blockIdx.x * TBN;

    float acc[4][4][4];
    #pragma unroll
    for (int mt = 0; mt < 4; mt++)
        #pragma unroll
        for (int nt = 0; nt < 4; nt++)
            #pragma unroll
            for (int r = 0; r < 4; r++) acc[mt][nt][r] = 0.f;

    for (int k0 = 0; k0 < K; k0 += TBK) {
        // load A tile 128x32 (1024 float4 slots)
        #pragma unroll
        for (int it = 0; it < 4; it++) {
            const int s  = tid + it * 256;
            const int r  = s >> 3;
            const int c4 = (s & 7) * 4;
            float4 a = *(const float4*)(A + (size_t)(row0 + r) * K + k0 + c4);
            *(float4*)&As[r][c4] = a;
        }
        // load B tile 32x128 (1024 float4 slots)
        #pragma unroll
        for (int it = 0; it < 4; it++) {
            const int s  = tid + it * 256;
            const int r  = s >> 5;
            const int c4 = (s & 31) * 4;
            float4 b = *(const float4*)(Bw + (size_t)(k0 + r) * N + col0 + c4);
            *(float4*)&Bs[r][c4] = b;
        }
        __syncthreads();

        #pragma unroll
        for (int kk = 0; kk < TBK; kk += 8) {
            unsigned ah[4][4], al[4][4];
            #pragma unroll
            for (int mt = 0; mt < 4; mt++) {
                const int m = wm + mt * 16;
                const float f0 = As[m + g    ][kk + tig    ];
                const float f1 = As[m + g + 8][kk + tig    ];
                const float f2 = As[m + g    ][kk + tig + 4];
                const float f3 = As[m + g + 8][kk + tig + 4];
                ah[mt][0] = f2tf32(f0); al[mt][0] = f2tf32(f0 - __uint_as_float(ah[mt][0]));
                ah[mt][1] = f2tf32(f1); al[mt][1] = f2tf32(f1 - __uint_as_float(ah[mt][1]));
                ah[mt][2] = f2tf32(f2); al[mt][2] = f2tf32(f2 - __uint_as_float(ah[mt][2]));
                ah[mt][3] = f2tf32(f3); al[mt][3] = f2tf32(f3 - __uint_as_float(ah[mt][3]));
            }
            unsigned bh[4][2], bl[4][2];
            #pragma unroll
            for (int nt = 0; nt < 4; nt++) {
                const int n = wn + nt * 8 + g;
                const float f0 = Bs[kk + tig    ][n];
                const float f1 = Bs[kk + tig + 4][n];
                bh[nt][0] = f2tf32(f0); bl[nt][0] = f2tf32(f0 - __uint_as_float(bh[nt][0]));
                bh[nt][1] = f2tf32(f1); bl[nt][1] = f2tf32(f1 - __uint_as_float(bh[nt][1]));
            }
            #pragma unroll
            for (int mt = 0; mt < 4; mt++)
                #pragma unroll
                for (int nt = 0; nt < 4; nt++) {
                    mma_tf32(acc[mt][nt], ah[mt][0], ah[mt][1], ah[mt][2], ah[mt][3],
                             bh[nt][0], bh[nt][1]);
                    mma_tf32(acc[mt][nt], al[mt][0], al[mt][1], al[mt][2], al[mt][3],
                             bh[nt][0], bh[nt][1]);
                    mma_tf32(acc[mt][nt], ah[mt][0], ah[mt][1], ah[mt][2], ah[mt][3],
                             bl[nt][0], bl[nt][1]);
                }
        }
        __syncthreads();
    }

    // epilogue
    #pragma unroll
    for (int mt = 0; mt < 4; mt++) {
        #pragma unroll
        for (int half = 0; half < 2; half++) {
            const int r = row0 + wm + mt * 16 + g + half * 8;
            const float rv = rowvec ? rowvec[r] : 0.f;
            #pragma unroll
            for (int nt = 0; nt < 4; nt++) {
                const int c = col0 + wn + nt * 8 + 2 * tig;
                float v0 = acc[mt][nt][half * 2 + 0];
                float v1 = acc[mt][nt][half * 2 + 1];
                if (bias)  { v0 += bias[c];  v1 += bias[c + 1]; }
                if (bias2) { v0 += bias2[c]; v1 += bias2[c + 1]; }
                if (rowvec) { v0 += rv * colvec[c]; v1 += rv * colvec[c + 1]; }
                if (gelu_flag) {
                    v0 = 0.5f * v0 * (1.f + erff(v0 * 0.70710678118654752f));
                    v1 = 0.5f * v1 * (1.f + erff(v1 * 0.70710678118654752f));
                }
                if (residual) {
                    float2 rr = *(const float2*)(residual + (size_t)r * N + c);
                    v0 += rr.x; v1 += rr.y;
                }
                float2 o; o.x = v0; o.y = v1;
                *(float2*)(C + (size_t)r * N + c) = o;
            }
        }
    }
}

// ---------------- LayerNorm: one block per token ---------------------------
__global__ __launch_bounds__(256) void ln_kernel(
    const float* __restrict__ x, const float* __restrict__ g,
    const float* __restrict__ bta, float* __restrict__ out)
{
    const int t = blockIdx.x;
    const int tid = threadIdx.x;
    const float* xr = x + (size_t)t * D_;

    float v[4];
    float s = 0.f, s2 = 0.f;
    #pragma unroll
    for (int i = 0; i < 4; i++) {
        v[i] = xr[tid + i*256];
        s  += v[i];
        s2 += v[i] * v[i];
    }
    #pragma unroll
    for (int o = 16; o; o >>= 1) {
        s  += __shfl_xor_sync(0xffffffffu, s,  o);
        s2 += __shfl_xor_sync(0xffffffffu, s2, o);
    }
    __shared__ float ss[8], ss2[8];
    if ((tid & 31) == 0) { ss[tid >> 5] = s; ss2[tid >> 5] = s2; }
    __syncthreads();
    s = 0.f; s2 = 0.f;
    #pragma unroll
    for (int w = 0; w < 8; w++) { s += ss[w]; s2 += ss2[w]; }

    const float mean = s * (1.f / D_);
    const float var  = s2 * (1.f / D_) - mean * mean;
    const float inv  = rsqrtf(var + 1e-5f);

    float* orow = out + (size_t)t * D_;
    #pragma unroll
    for (int i = 0; i < 4; i++) {
        const int c = tid + i*256;
        orow[c] = (v[i] - mean) * inv * g[c] + bta[c];
    }
}

// ---------------- RoPE (in-place, one thread owns the rotation pair) -------
__global__ __launch_bounds__(256) void rope_kernel(float* __restrict__ x)
{
    const int idx = blockIdx.x * 256 + threadIdx.x;   // T_*H_*32 = 1,048,576
    const int j = idx & 31;
    const int h = (idx >> 5) & 15;
    const int t = idx >> 9;                            // token 0..2047
    const int s = t >> 2;                              // sequence position (/B_)

    const float inv_freq = powf(10000.f, -((float)(2*j)) * (1.f / HD_));
    float sn, c;
    sincosf((float)s * inv_freq, &sn, &c);

    float* base = x + (size_t)t * D_ + h * HD_;
    const float x1 = base[j];
    const float x2 = base[j + 32];
    base[j]      = x1 * c - x2 * sn;
    base[j + 32] = x2 * c + x1 * sn;
}

// ---------------- scores = scale * Q K^T, masked ---------------------------
// grid (S/64, S/64, B*H), block 256; per-thread 4x4 output
__global__ __launch_bounds__(256) void qk_kernel(
    const float* __restrict__ q, const float* __restrict__ k,
    const int* __restrict__ mask, float* __restrict__ scores)
{
    const int bh = blockIdx.z;
    const int b = bh >> 4;
    const int h = bh & 15;
    const int qt = blockIdx.y * 64;
    const int kt = blockIdx.x * 64;

    __shared__ float Qs[HD_][65];
    __shared__ float Ks[HD_][65];

    const int tid = threadIdx.x;
    const int ty = tid >> 4, tx = tid & 15;
    const int lr = tid >> 4;
    const int lc = (tid & 15) * 4;

    #pragma unroll
    for (int it = 0; it < 4; it++) {
        const int m = lr + it*16;
        float4 a = *(const float4*)(q + ((size_t)(qt + m) * B_ + b) * D_ + h*HD_ + lc);
        Qs[lc+0][m]=a.x; Qs[lc+1][m]=a.y; Qs[lc+2][m]=a.z; Qs[lc+3][m]=a.w;
        float4 bb = *(const float4*)(k + ((size_t)(kt + m) * B_ + b) * D_ + h*HD_ + lc);
        Ks[lc+0][m]=bb.x; Ks[lc+1][m]=bb.y; Ks[lc+2][m]=bb.z; Ks[lc+3][m]=bb.w;
    }
    __syncthreads();

    float acc[4][4];
    #pragma unroll
    for (int i = 0; i < 4; i++)
        #pragma unroll
        for (int j = 0; j < 4; j++) acc[i][j] = 0.f;

    #pragma unroll
    for (int kk = 0; kk < HD_; kk++) {
        float av[4], bv[4];
        #pragma unroll
        for (int i = 0; i < 4; i++) av[i] = Qs[kk][ty*4 + i];
        #pragma unroll
        for (int j = 0; j < 4; j++) bv[j] = Ks[kk][tx*4 + j];
        #pragma unroll
        for (int i = 0; i < 4; i++)
            #pragma unroll
            for (int j = 0; j < 4; j++)
                acc[i][j] = fmaf(av[i], bv[j], acc[i][j]);
    }

    const float scale = 0.125f;  // 1/sqrt(64)
    #pragma unroll
    for (int i = 0; i < 4; i++) {
        const int qpos = qt + ty*4 + i;
        float* out = scores + ((size_t)bh * S_ + qpos) * S_;
        #pragma unroll
        for (int j = 0; j < 4; j++) {
            const int kpos = kt + tx*4 + j;
            float vsc = acc[i][j] * scale;
            if (mask[b * S_ + kpos] != 0) vsc = -1e30f;
            out[kpos] = vsc;
        }
    }
}

// ---------------- row softmax over 512 keys --------------------------------
__global__ __launch_bounds__(128) void softmax_kernel(float* __restrict__ scores)
{
    const size_t row = blockIdx.x;
    float* p = scores + row * S_;
    const int tid = threadIdx.x;

    float vals[4];
    float m = -3.0e38f;
    #pragma unroll
    for (int i = 0; i < 4; i++) { vals[i] = p[tid + i*128]; m = fmaxf(m, vals[i]); }
    #pragma unroll
    for (int o = 16; o; o >>= 1) m = fmaxf(m, __shfl_xor_sync(0xffffffffu, m, o));
    __shared__ float sm[4], ssum[4];
    if ((tid & 31) == 0) sm[tid >> 5] = m;
    __syncthreads();
    m = fmaxf(fmaxf(sm[0], sm[1]), fmaxf(sm[2], sm[3]));

    float s = 0.f;
    #pragma unroll
    for (int i = 0; i < 4; i++) { vals[i] = __expf(vals[i] - m); s += vals[i]; }
    #pragma unroll
    for (int o = 16; o; o >>= 1) s += __shfl_xor_sync(0xffffffffu, s, o);
    if ((tid & 31) == 0) ssum[tid >> 5] = s;
    __syncthreads();
    const float inv = 1.f / (ssum[0] + ssum[1] + ssum[2] + ssum[3]);

    #pragma unroll
    for (int i = 0; i < 4; i++) p[tid + i*128] = vals[i] * inv;
}

// ---------------- attn = probs @ V, scattered to [t, d] layout -------------
// grid (1, S/64, B*H), block 256
__global__ __launch_bounds__(256) void pv_kernel(
    const float* __restrict__ scores, const float* __restrict__ v,
    float* __restrict__ attn)
{
    const int bh = blockIdx.z;
    const int b = bh >> 4, h = bh & 15;
    const int qt = blockIdx.y * 64;

    __shared__ float Ps[32][65];
    __shared__ float Vs[32][64];

    const int tid = threadIdx.x;
    const int ty = tid >> 4, tx = tid & 15;
    const int pr = tid >> 3;           // 0..31
    const int pc = (tid & 7) * 4;      // 0..28
    const int vr = tid >> 4;           // 0..15
    const int vc = (tid & 15) * 4;     // 0..60

    float acc[4][4];
    #pragma unroll
    for (int i = 0; i < 4; i++)
        #pragma unroll
        for (int j = 0; j < 4; j++) acc[i][j] = 0.f;

    for (int kt = 0; kt < S_; kt += 32) {
        #pragma unroll
        for (int it = 0; it < 2; it++) {
            const int m = pr + it*32;   // q row 0..63
            float4 a = *(const float4*)(scores + ((size_t)bh*S_ + qt + m)*S_ + kt + pc);
            Ps[pc+0][m]=a.x; Ps[pc+1][m]=a.y; Ps[pc+2][m]=a.z; Ps[pc+3][m]=a.w;
        }
        #pragma unroll
        for (int it = 0; it < 2; it++) {
            const int kr = vr + it*16;  // k row 0..31
            float4 bb = *(const float4*)(v + ((size_t)(kt + kr)*B_ + b)*D_ + h*HD_ + vc);
            *(float4*)&Vs[kr][vc] = bb;
        }
        __syncthreads();

        #pragma unroll
        for (int kk = 0; kk < 32; kk++) {
            float av[4], bv[4];
            #pragma unroll
            for (int i = 0; i < 4; i++) av[i] = Ps[kk][ty*4 + i];
            #pragma unroll
            for (int j = 0; j < 4; j++) bv[j] = Vs[kk][tx*4 + j];
            #pragma unroll
            for (int i = 0; i < 4; i++)
                #pragma unroll
                for (int j = 0; j < 4; j++)
                    acc[i][j] = fmaf(av[i], bv[j], acc[i][j]);
        }
        __syncthreads();
    }

    #pragma unroll
    for (int i = 0; i < 4; i++) {
        const int qpos = qt + ty*4 + i;
        float* orow = attn + ((size_t)qpos * B_ + b) * D_ + h*HD_;
        #pragma unroll
        for (int j = 0; j < 4; j++)
            orow[tx*4 + j] = acc[i][j];
    }
}

// ---------------- host orchestration ---------------------------------------
extern "C" void kernel_launch(void* const* d_in, const int* in_sizes, int n_in,
                              void* d_out, int out_size)
{
    (void)in_sizes; (void)n_in; (void)out_size;

    const float* segments  = (const float*)d_in[0];
    const float* durations = (const float*)d_in[1];
    const int*   padmask   = (const int*)d_in[2];   // bool promoted to int32
    const float* Wproj = (const float*)d_in[3];
    const float* bproj = (const float*)d_in[4];
    const float* Wdur  = (const float*)d_in[5];
    const float* bdur  = (const float*)d_in[6];
    const float* ln1_g = (const float*)d_in[7];
    const float* ln1_b = (const float*)d_in[8];
    const float* Wq = (const float*)d_in[9];
    const float* bq = (const float*)d_in[10];
    const float* Wk = (const float*)d_in[11];
    const float* bk = (const float*)d_in[12];
    const float* Wv = (const float*)d_in[13];
    const float* bv = (const float*)d_in[14];
    const float* Wo = (const float*)d_in[15];
    const float* bo = (const float*)d_in[16];
    const float* ln2_g = (const float*)d_in[17];
    const float* ln2_b = (const float*)d_in[18];
    const float* Wff1 = (const float*)d_in[19];
    const float* bff1 = (const float*)d_in[20];
    const float* Wff2 = (const float*)d_in[21];
    const float* bff2 = (const float*)d_in[22];

    float* x = (float*)d_out;   // residual stream lives in d_out

    float *h, *q, *k, *v, *attn, *ff, *scores;
    cudaGetSymbolAddress((void**)&h,      g_h);
    cudaGetSymbolAddress((void**)&q,      g_q);
    cudaGetSymbolAddress((void**)&k,      g_k);
    cudaGetSymbolAddress((void**)&v,      g_v);
    cudaGetSymbolAddress((void**)&attn,   g_attn);
    cudaGetSymbolAddress((void**)&ff,     g_ff);
    cudaGetSymbolAddress((void**)&scores, g_scores);

    const dim3 blk(256);

    // x = segments @ Wproj + bproj + durations*Wdur + bdur
    gemm_tc<<<dim3(D_/TBN, T_/TBM), blk>>>(
        segments, Wproj, bproj, bdur, durations, Wdur, nullptr,
        x, T_, D_, DIN_, 0);

    for (int l = 0; l < L_; l++) {
        const float* wq = Wq + (size_t)l*D_*D_;
        const float* wk = Wk + (size_t)l*D_*D_;
        const float* wv = Wv + (size_t)l*D_*D_;
        const float* wo = Wo + (size_t)l*D_*D_;
        const float* w1 = Wff1 + (size_t)l*D_*F_;
        const float* w2 = Wff2 + (size_t)l*F_*D_;

        ln_kernel<<<T_, 256>>>(x, ln1_g + l*D_, ln1_b + l*D_, h);

        gemm_tc<<<dim3(D_/TBN, T_/TBM), blk>>>(h, wq, bq + l*D_,
            nullptr, nullptr, nullptr, nullptr, q, T_, D_, D_, 0);
        gemm_tc<<<dim3(D_/TBN, T_/TBM), blk>>>(h, wk, bk + l*D_,
            nullptr, nullptr, nullptr, nullptr, k, T_, D_, D_, 0);
        gemm_tc<<<dim3(D_/TBN, T_/TBM), blk>>>(h, wv, bv + l*D_,
            nullptr, nullptr, nullptr, nullptr, v, T_, D_, D_, 0);

        rope_kernel<<<(T_*H_*32)/256, 256>>>(q);
        rope_kernel<<<(T_*H_*32)/256, 256>>>(k);

        qk_kernel<<<dim3(S_/64, S_/64, B_*H_), blk>>>(q, k, padmask, scores);
        softmax_kernel<<<B_*H_*S_, 128>>>(scores);
        pv_kernel<<<dim3(1, S_/64, B_*H_), blk>>>(scores, v, attn);

        // x = x + attn @ Wo + bo
        gemm_tc<<<dim3(D_/TBN, T_/TBM), blk>>>(attn, wo, bo + l*D_,
            nullptr, nullptr, nullptr, x, x, T_, D_, D_, 0);

        ln_kernel<<<T_, 256>>>(x, ln2_g + l*D_, ln2_b + l*D_, h);

        // ff = gelu(h @ W1 + b1)
        gemm_tc<<<dim3(F_/TBN, T_/TBM), blk>>>(h, w1, bff1 + l*F_,
            nullptr, nullptr, nullptr, nullptr, ff, T_, F_, D_, 1);

        // x = x + ff @ W2 + b2
        gemm_tc<<<dim3(D_/TBN, T_/TBM), blk>>>(ff, w2, bff2 + l*D_,
            nullptr, nullptr, nullptr, x, x, T_, D_, F_, 0);
    }
}

// round 4
// speedup vs baseline: 1.6671x; 1.1251x over previous
#include <cuda_runtime.h>
#include <math.h>

#define L_   12
#define S_   512
#define B_   4
#define DIN_ 768
#define D_   1024
#define H_   16
#define F_   4096
#define HD_  64
#define T_   (S_*B_)   // 2048 tokens

// ---------------- scratch (static device globals; no runtime allocation) ----
__device__ float g_h[T_*D_];
__device__ float g_q[T_*D_];
__device__ float g_k[T_*D_];
__device__ float g_v[T_*D_];
__device__ float g_attn[T_*D_];
__device__ float g_ff[(size_t)T_*F_];
__device__ float g_scores[(size_t)B_*H_*S_*S_];   // 67 MB

// ---------------- tf32 helpers ---------------------------------------------
__device__ __forceinline__ unsigned f2tf32(float f) {
    unsigned u;
    asm("cvt.rna.tf32.f32 %0, %1;" : "=r"(u) : "f"(f));
    return u;
}

__device__ __forceinline__ void mma_tf32(float c[4],
    unsigned a0, unsigned a1, unsigned a2, unsigned a3,
    unsigned b0, unsigned b1)
{
    asm volatile(
        "mma.sync.aligned.m16n8k8.row.col.f32.tf32.tf32.f32 "
        "{%0,%1,%2,%3}, {%4,%5,%6,%7}, {%8,%9}, {%0,%1,%2,%3};"
        : "+f"(c[0]), "+f"(c[1]), "+f"(c[2]), "+f"(c[3])
        : "r"(a0), "r"(a1), "r"(a2), "r"(a3), "r"(b0), "r"(b1));
}

__device__ __forceinline__ void split_tf32(float f, float& hi, float& lo) {
    unsigned h = f2tf32(f);
    hi = __uint_as_float(h);
    lo = __uint_as_float(f2tf32(f - hi));
}

// ---------------- tensor-core GEMM (3xTF32, split hoisted to smem) ---------
// C = A[MxK] @ W[KxN] + bias[c] + bias2[c] + rowvec[r]*colvec[c];
// optional exact GELU; + residual[r,c]
// block tile 128x128x32, 8 warps (2x4), warp tile 64x32, m16n8k8
// smem: Ah/Al [128][36], Bh/Bl [32][136] floats in dynamic smem (71,680 B)
#define TBM 128
#define TBN 128
#define TBK 32
#define A_STRIDE 36
#define B_STRIDE 136
#define OFF_AL  (TBM*A_STRIDE)             // 4608
#define OFF_BH  (2*TBM*A_STRIDE)           // 9216
#define OFF_BL  (2*TBM*A_STRIDE + TBK*B_STRIDE)  // 13568
#define SMEM_FLOATS (2*TBM*A_STRIDE + 2*TBK*B_STRIDE)   // 17920
#define SMEM_BYTES  (SMEM_FLOATS*4)        // 71680

__global__ __launch_bounds__(256, 1) void gemm_tc(
    const float* __restrict__ A, const float* __restrict__ Bw,
    const float* __restrict__ bias, const float* __restrict__ bias2,
    const float* __restrict__ rowvec, const float* __restrict__ colvec,
    const float* __restrict__ residual,
    float* __restrict__ C, int M, int N, int K, int gelu_flag)
{
    extern __shared__ float sm[];
    float* Ah = sm;
    float* Al = sm + OFF_AL;
    float* Bh = sm + OFF_BH;
    float* Bl = sm + OFF_BL;

    const int tid  = threadIdx.x;
    const int warp = tid >> 5;
    const int lane = tid & 31;
    const int g    = lane >> 2;      // 0..7
    const int tig  = lane & 3;       // 0..3
    const int wm   = (warp >> 2) * 64;   // 0 or 64
    const int wn   = (warp & 3) * 32;    // 0,32,64,96

    const int row0 = blockIdx.y * TBM;
    const int col0 = blockIdx.x * TBN;

    // A-load indexing: 4 float4 per thread
    const int a_r  = tid >> 3;           // 0..31 (plus it*? no: s covers via it)
    const int a_c4 = (tid & 7) * 4;
    const int b_r  = tid >> 5;
    const int b_c4 = (tid & 31) * 4;

    float acc[4][4][4];
    #pragma unroll
    for (int mt = 0; mt < 4; mt++)
        #pragma unroll
        for (int nt = 0; nt < 4; nt++)
            #pragma unroll
            for (int r = 0; r < 4; r++) acc[mt][nt][r] = 0.f;

    float4 pa[4], pb[4];

    // ---- prologue: load tile 0 and split into smem
    #pragma unroll
    for (int it = 0; it < 4; it++) {
        const int s = tid + it * 256;
        pa[it] = *(const float4*)(A + (size_t)(row0 + (s >> 3)) * K + (s & 7) * 4);
        pb[it] = *(const float4*)(Bw + (size_t)(s >> 5) * N + col0 + (s & 31) * 4);
    }
    #pragma unroll
    for (int it = 0; it < 4; it++) {
        const int s = tid + it * 256;
        const int ar = s >> 3, ac = (s & 7) * 4;
        float4 h4, l4;
        split_tf32(pa[it].x, h4.x, l4.x); split_tf32(pa[it].y, h4.y, l4.y);
        split_tf32(pa[it].z, h4.z, l4.z); split_tf32(pa[it].w, h4.w, l4.w);
        *(float4*)&Ah[ar * A_STRIDE + ac] = h4;
        *(float4*)&Al[ar * A_STRIDE + ac] = l4;
        const int br = s >> 5, bc = (s & 31) * 4;
        split_tf32(pb[it].x, h4.x, l4.x); split_tf32(pb[it].y, h4.y, l4.y);
        split_tf32(pb[it].z, h4.z, l4.z); split_tf32(pb[it].w, h4.w, l4.w);
        *(float4*)&Bh[br * B_STRIDE + bc] = h4;
        *(float4*)&Bl[br * B_STRIDE + bc] = l4;
    }
    __syncthreads();

    const int nk = K / TBK;
    for (int ki = 0; ki < nk; ki++) {
        // ---- prefetch next tile into registers (latency hidden by MMAs)
        if (ki + 1 < nk) {
            const int k0n = (ki + 1) * TBK;
            #pragma unroll
            for (int it = 0; it < 4; it++) {
                const int s = tid + it * 256;
                pa[it] = *(const float4*)(A + (size_t)(row0 + (s >> 3)) * K + k0n + (s & 7) * 4);
                pb[it] = *(const float4*)(Bw + (size_t)(k0n + (s >> 5)) * N + col0 + (s & 31) * 4);
            }
        }

        // ---- compute from smem (no conversions in this loop)
        #pragma unroll
        for (int kk = 0; kk < TBK; kk += 8) {
            unsigned ah[4][4], al[4][4];
            #pragma unroll
            for (int mt = 0; mt < 4; mt++) {
                const int m = wm + mt * 16;
                const int r0i = (m + g) * A_STRIDE + kk + tig;
                const int r1i = (m + g + 8) * A_STRIDE + kk + tig;
                ah[mt][0] = __float_as_uint(Ah[r0i]);
                ah[mt][1] = __float_as_uint(Ah[r1i]);
                ah[mt][2] = __float_as_uint(Ah[r0i + 4]);
                ah[mt][3] = __float_as_uint(Ah[r1i + 4]);
                al[mt][0] = __float_as_uint(Al[r0i]);
                al[mt][1] = __float_as_uint(Al[r1i]);
                al[mt][2] = __float_as_uint(Al[r0i + 4]);
                al[mt][3] = __float_as_uint(Al[r1i + 4]);
            }
            unsigned bh[4][2], bl[4][2];
            #pragma unroll
            for (int nt = 0; nt < 4; nt++) {
                const int n = wn + nt * 8 + g;
                const int c0i = (kk + tig) * B_STRIDE + n;
                const int c1i = (kk + tig + 4) * B_STRIDE + n;
                bh[nt][0] = __float_as_uint(Bh[c0i]);
                bh[nt][1] = __float_as_uint(Bh[c1i]);
                bl[nt][0] = __float_as_uint(Bl[c0i]);
                bl[nt][1] = __float_as_uint(Bl[c1i]);
            }
            #pragma unroll
            for (int mt = 0; mt < 4; mt++)
                #pragma unroll
                for (int nt = 0; nt < 4; nt++) {
                    mma_tf32(acc[mt][nt], ah[mt][0], ah[mt][1], ah[mt][2], ah[mt][3],
                             bh[nt][0], bh[nt][1]);
                    mma_tf32(acc[mt][nt], al[mt][0], al[mt][1], al[mt][2], al[mt][3],
                             bh[nt][0], bh[nt][1]);
                    mma_tf32(acc[mt][nt], ah[mt][0], ah[mt][1], ah[mt][2], ah[mt][3],
                             bl[nt][0], bl[nt][1]);
                }
        }
        __syncthreads();

        // ---- store prefetched tile (split) into smem
        if (ki + 1 < nk) {
            #pragma unroll
            for (int it = 0; it < 4; it++) {
                const int s = tid + it * 256;
                const int ar = s >> 3, ac = (s & 7) * 4;
                float4 h4, l4;
                split_tf32(pa[it].x, h4.x, l4.x); split_tf32(pa[it].y, h4.y, l4.y);
                split_tf32(pa[it].z, h4.z, l4.z); split_tf32(pa[it].w, h4.w, l4.w);
                *(float4*)&Ah[ar * A_STRIDE + ac] = h4;
                *(float4*)&Al[ar * A_STRIDE + ac] = l4;
                const int br = s >> 5, bc = (s & 31) * 4;
                split_tf32(pb[it].x, h4.x, l4.x); split_tf32(pb[it].y, h4.y, l4.y);
                split_tf32(pb[it].z, h4.z, l4.z); split_tf32(pb[it].w, h4.w, l4.w);
                *(float4*)&Bh[br * B_STRIDE + bc] = h4;
                *(float4*)&Bl[br * B_STRIDE + bc] = l4;
            }
            __syncthreads();
        }
    }

    // ---- epilogue
    #pragma unroll
    for (int mt = 0; mt < 4; mt++) {
        #pragma unroll
        for (int half = 0; half < 2; half++) {
            const int r = row0 + wm + mt * 16 + g + half * 8;
            const float rv = rowvec ? rowvec[r] : 0.f;
            #pragma unroll
            for (int nt = 0; nt < 4; nt++) {
                const int c = col0 + wn + nt * 8 + 2 * tig;
                float v0 = acc[mt][nt][half * 2 + 0];
                float v1 = acc[mt][nt][half * 2 + 1];
                if (bias)  { v0 += bias[c];  v1 += bias[c + 1]; }
                if (bias2) { v0 += bias2[c]; v1 += bias2[c + 1]; }
                if (rowvec) { v0 += rv * colvec[c]; v1 += rv * colvec[c + 1]; }
                if (gelu_flag) {
                    v0 = 0.5f * v0 * (1.f + erff(v0 * 0.70710678118654752f));
                    v1 = 0.5f * v1 * (1.f + erff(v1 * 0.70710678118654752f));
                }
                if (residual) {
                    float2 rr = *(const float2*)(residual + (size_t)r * N + c);
                    v0 += rr.x; v1 += rr.y;
                }
                float2 o; o.x = v0; o.y = v1;
                *(float2*)(C + (size_t)r * N + c) = o;
            }
        }
    }
}

// ---------------- LayerNorm: one block per token ---------------------------
__global__ __launch_bounds__(256) void ln_kernel(
    const float* __restrict__ x, const float* __restrict__ g,
    const float* __restrict__ bta, float* __restrict__ out)
{
    const int t = blockIdx.x;
    const int tid = threadIdx.x;
    const float* xr = x + (size_t)t * D_;

    float v[4];
    float s = 0.f, s2 = 0.f;
    #pragma unroll
    for (int i = 0; i < 4; i++) {
        v[i] = xr[tid + i*256];
        s  += v[i];
        s2 += v[i] * v[i];
    }
    #pragma unroll
    for (int o = 16; o; o >>= 1) {
        s  += __shfl_xor_sync(0xffffffffu, s,  o);
        s2 += __shfl_xor_sync(0xffffffffu, s2, o);
    }
    __shared__ float ss[8], ss2[8];
    if ((tid & 31) == 0) { ss[tid >> 5] = s; ss2[tid >> 5] = s2; }
    __syncthreads();
    s = 0.f; s2 = 0.f;
    #pragma unroll
    for (int w = 0; w < 8; w++) { s += ss[w]; s2 += ss2[w]; }

    const float mean = s * (1.f / D_);
    const float var  = s2 * (1.f / D_) - mean * mean;
    const float inv  = rsqrtf(var + 1e-5f);

    float* orow = out + (size_t)t * D_;
    #pragma unroll
    for (int i = 0; i < 4; i++) {
        const int c = tid + i*256;
        orow[c] = (v[i] - mean) * inv * g[c] + bta[c];
    }
}

// ---------------- RoPE (in-place, one thread owns the rotation pair) -------
__global__ __launch_bounds__(256) void rope_kernel(float* __restrict__ x)
{
    const int idx = blockIdx.x * 256 + threadIdx.x;   // T_*H_*32 = 1,048,576
    const int j = idx & 31;
    const int h = (idx >> 5) & 15;
    const int t = idx >> 9;                            // token 0..2047
    const int s = t >> 2;                              // sequence position (/B_)

    const float inv_freq = powf(10000.f, -((float)(2*j)) * (1.f / HD_));
    float sn, c;
    sincosf((float)s * inv_freq, &sn, &c);

    float* base = x + (size_t)t * D_ + h * HD_;
    const float x1 = base[j];
    const float x2 = base[j + 32];
    base[j]      = x1 * c - x2 * sn;
    base[j + 32] = x2 * c + x1 * sn;
}

// ---------------- scores = scale * Q K^T, masked ---------------------------
// grid (S/64, S/64, B*H), block 256; per-thread 4x4 output
__global__ __launch_bounds__(256) void qk_kernel(
    const float* __restrict__ q, const float* __restrict__ k,
    const int* __restrict__ mask, float* __restrict__ scores)
{
    const int bh = blockIdx.z;
    const int b = bh >> 4;
    const int h = bh & 15;
    const int qt = blockIdx.y * 64;
    const int kt = blockIdx.x * 64;

    __shared__ float Qs[HD_][65];
    __shared__ float Ks[HD_][65];

    const int tid = threadIdx.x;
    const int ty = tid >> 4, tx = tid & 15;
    const int lr = tid >> 4;
    const int lc = (tid & 15) * 4;

    #pragma unroll
    for (int it = 0; it < 4; it++) {
        const int m = lr + it*16;
        float4 a = *(const float4*)(q + ((size_t)(qt + m) * B_ + b) * D_ + h*HD_ + lc);
        Qs[lc+0][m]=a.x; Qs[lc+1][m]=a.y; Qs[lc+2][m]=a.z; Qs[lc+3][m]=a.w;
        float4 bb = *(const float4*)(k + ((size_t)(kt + m) * B_ + b) * D_ + h*HD_ + lc);
        Ks[lc+0][m]=bb.x; Ks[lc+1][m]=bb.y; Ks[lc+2][m]=bb.z; Ks[lc+3][m]=bb.w;
    }
    __syncthreads();

    float acc[4][4];
    #pragma unroll
    for (int i = 0; i < 4; i++)
        #pragma unroll
        for (int j = 0; j < 4; j++) acc[i][j] = 0.f;

    #pragma unroll
    for (int kk = 0; kk < HD_; kk++) {
        float av[4], bv[4];
        #pragma unroll
        for (int i = 0; i < 4; i++) av[i] = Qs[kk][ty*4 + i];
        #pragma unroll
        for (int j = 0; j < 4; j++) bv[j] = Ks[kk][tx*4 + j];
        #pragma unroll
        for (int i = 0; i < 4; i++)
            #pragma unroll
            for (int j = 0; j < 4; j++)
                acc[i][j] = fmaf(av[i], bv[j], acc[i][j]);
    }

    const float scale = 0.125f;  // 1/sqrt(64)
    #pragma unroll
    for (int i = 0; i < 4; i++) {
        const int qpos = qt + ty*4 + i;
        float* out = scores + ((size_t)bh * S_ + qpos) * S_;
        #pragma unroll
        for (int j = 0; j < 4; j++) {
            const int kpos = kt + tx*4 + j;
            float vsc = acc[i][j] * scale;
            if (mask[b * S_ + kpos] != 0) vsc = -1e30f;
            out[kpos] = vsc;
        }
    }
}

// ---------------- row softmax over 512 keys --------------------------------
__global__ __launch_bounds__(128) void softmax_kernel(float* __restrict__ scores)
{
    const size_t row = blockIdx.x;
    float* p = scores + row * S_;
    const int tid = threadIdx.x;

    float vals[4];
    float m = -3.0e38f;
    #pragma unroll
    for (int i = 0; i < 4; i++) { vals[i] = p[tid + i*128]; m = fmaxf(m, vals[i]); }
    #pragma unroll
    for (int o = 16; o; o >>= 1) m = fmaxf(m, __shfl_xor_sync(0xffffffffu, m, o));
    __shared__ float sm[4], ssum[4];
    if ((tid & 31) == 0) sm[tid >> 5] = m;
    __syncthreads();
    m = fmaxf(fmaxf(sm[0], sm[1]), fmaxf(sm[2], sm[3]));

    float s = 0.f;
    #pragma unroll
    for (int i = 0; i < 4; i++) { vals[i] = __expf(vals[i] - m); s += vals[i]; }
    #pragma unroll
    for (int o = 16; o; o >>= 1) s += __shfl_xor_sync(0xffffffffu, s, o);
    if ((tid & 31) == 0) ssum[tid >> 5] = s;
    __syncthreads();
    const float inv = 1.f / (ssum[0] + ssum[1] + ssum[2] + ssum[3]);

    #pragma unroll
    for (int i = 0; i < 4; i++) p[tid + i*128] = vals[i] * inv;
}

// ---------------- attn = probs @ V, scattered to [t, d] layout -------------
// grid (1, S/64, B*H), block 256
__global__ __launch_bounds__(256) void pv_kernel(
    const float* __restrict__ scores, const float* __restrict__ v,
    float* __restrict__ attn)
{
    const int bh = blockIdx.z;
    const int b = bh >> 4, h = bh & 15;
    const int qt = blockIdx.y * 64;

    __shared__ float Ps[32][65];
    __shared__ float Vs[32][64];

    const int tid = threadIdx.x;
    const int ty = tid >> 4, tx = tid & 15;
    const int pr = tid >> 3;           // 0..31
    const int pc = (tid & 7) * 4;      // 0..28
    const int vr = tid >> 4;           // 0..15
    const int vc = (tid & 15) * 4;     // 0..60

    float acc[4][4];
    #pragma unroll
    for (int i = 0; i < 4; i++)
        #pragma unroll
        for (int j = 0; j < 4; j++) acc[i][j] = 0.f;

    for (int kt = 0; kt < S_; kt += 32) {
        #pragma unroll
        for (int it = 0; it < 2; it++) {
            const int m = pr + it*32;   // q row 0..63
            float4 a = *(const float4*)(scores + ((size_t)bh*S_ + qt + m)*S_ + kt + pc);
            Ps[pc+0][m]=a.x; Ps[pc+1][m]=a.y; Ps[pc+2][m]=a.z; Ps[pc+3][m]=a.w;
        }
        #pragma unroll
        for (int it = 0; it < 2; it++) {
            const int kr = vr + it*16;  // k row 0..31
            float4 bb = *(const float4*)(v + ((size_t)(kt + kr)*B_ + b)*D_ + h*HD_ + vc);
            *(float4*)&Vs[kr][vc] = bb;
        }
        __syncthreads();

        #pragma unroll
        for (int kk = 0; kk < 32; kk++) {
            float av[4], bv[4];
            #pragma unroll
            for (int i = 0; i < 4; i++) av[i] = Ps[kk][ty*4 + i];
            #pragma unroll
            for (int j = 0; j < 4; j++) bv[j] = Vs[kk][tx*4 + j];
            #pragma unroll
            for (int i = 0; i < 4; i++)
                #pragma unroll
                for (int j = 0; j < 4; j++)
                    acc[i][j] = fmaf(av[i], bv[j], acc[i][j]);
        }
        __syncthreads();
    }

    #pragma unroll
    for (int i = 0; i < 4; i++) {
        const int qpos = qt + ty*4 + i;
        float* orow = attn + ((size_t)qpos * B_ + b) * D_ + h*HD_;
        #pragma unroll
        for (int j = 0; j < 4; j++)
            orow[tx*4 + j] = acc[i][j];
    }
}

// ---------------- host orchestration ---------------------------------------
extern "C" void kernel_launch(void* const* d_in, const int* in_sizes, int n_in,
                              void* d_out, int out_size)
{
    (void)in_sizes; (void)n_in; (void)out_size;

    const float* segments  = (const float*)d_in[0];
    const float* durations = (const float*)d_in[1];
    const int*   padmask   = (const int*)d_in[2];   // bool promoted to int32
    const float* Wproj = (const float*)d_in[3];
    const float* bproj = (const float*)d_in[4];
    const float* Wdur  = (const float*)d_in[5];
    const float* bdur  = (const float*)d_in[6];
    const float* ln1_g = (const float*)d_in[7];
    const float* ln1_b = (const float*)d_in[8];
    const float* Wq = (const float*)d_in[9];
    const float* bq = (const float*)d_in[10];
    const float* Wk = (const float*)d_in[11];
    const float* bk = (const float*)d_in[12];
    const float* Wv = (const float*)d_in[13];
    const float* bv = (const float*)d_in[14];
    const float* Wo = (const float*)d_in[15];
    const float* bo = (const float*)d_in[16];
    const float* ln2_g = (const float*)d_in[17];
    const float* ln2_b = (const float*)d_in[18];
    const float* Wff1 = (const float*)d_in[19];
    const float* bff1 = (const float*)d_in[20];
    const float* Wff2 = (const float*)d_in[21];
    const float* bff2 = (const float*)d_in[22];

    float* x = (float*)d_out;   // residual stream lives in d_out

    float *h, *q, *k, *v, *attn, *ff, *scores;
    cudaGetSymbolAddress((void**)&h,      g_h);
    cudaGetSymbolAddress((void**)&q,      g_q);
    cudaGetSymbolAddress((void**)&k,      g_k);
    cudaGetSymbolAddress((void**)&v,      g_v);
    cudaGetSymbolAddress((void**)&attn,   g_attn);
    cudaGetSymbolAddress((void**)&ff,     g_ff);
    cudaGetSymbolAddress((void**)&scores, g_scores);

    cudaFuncSetAttribute(gemm_tc,
        cudaFuncAttributeMaxDynamicSharedMemorySize, SMEM_BYTES);

    const dim3 blk(256);

    // x = segments @ Wproj + bproj + durations*Wdur + bdur
    gemm_tc<<<dim3(D_/TBN, T_/TBM), blk, SMEM_BYTES>>>(
        segments, Wproj, bproj, bdur, durations, Wdur, nullptr,
        x, T_, D_, DIN_, 0);

    for (int l = 0; l < L_; l++) {
        const float* wq = Wq + (size_t)l*D_*D_;
        const float* wk = Wk + (size_t)l*D_*D_;
        const float* wv = Wv + (size_t)l*D_*D_;
        const float* wo = Wo + (size_t)l*D_*D_;
        const float* w1 = Wff1 + (size_t)l*D_*F_;
        const float* w2 = Wff2 + (size_t)l*F_*D_;

        ln_kernel<<<T_, 256>>>(x, ln1_g + l*D_, ln1_b + l*D_, h);

        gemm_tc<<<dim3(D_/TBN, T_/TBM), blk, SMEM_BYTES>>>(h, wq, bq + l*D_,
            nullptr, nullptr, nullptr, nullptr, q, T_, D_, D_, 0);
        gemm_tc<<<dim3(D_/TBN, T_/TBM), blk, SMEM_BYTES>>>(h, wk, bk + l*D_,
            nullptr, nullptr, nullptr, nullptr, k, T_, D_, D_, 0);
        gemm_tc<<<dim3(D_/TBN, T_/TBM), blk, SMEM_BYTES>>>(h, wv, bv + l*D_,
            nullptr, nullptr, nullptr, nullptr, v, T_, D_, D_, 0);

        rope_kernel<<<(T_*H_*32)/256, 256>>>(q);
        rope_kernel<<<(T_*H_*32)/256, 256>>>(k);

        qk_kernel<<<dim3(S_/64, S_/64, B_*H_), blk>>>(q, k, padmask, scores);
        softmax_kernel<<<B_*H_*S_, 128>>>(scores);
        pv_kernel<<<dim3(1, S_/64, B_*H_), blk>>>(scores, v, attn);

        // x = x + attn @ Wo + bo
        gemm_tc<<<dim3(D_/TBN, T_/TBM), blk, SMEM_BYTES>>>(attn, wo, bo + l*D_,
            nullptr, nullptr, nullptr, x, x, T_, D_, D_, 0);

        ln_kernel<<<T_, 256>>>(x, ln2_g + l*D_, ln2_b + l*D_, h);

        // ff = gelu(h @ W1 + b1)
        gemm_tc<<<dim3(F_/TBN, T_/TBM), blk, SMEM_BYTES>>>(h, w1, bff1 + l*F_,
            nullptr, nullptr, nullptr, nullptr, ff, T_, F_, D_, 1);

        // x = x + ff @ W2 + b2
        gemm_tc<<<dim3(D_/TBN, T_/TBM), blk, SMEM_BYTES>>>(ff, w2, bff2 + l*D_,
            nullptr, nullptr, nullptr, x, x, T_, D_, F_, 0);
    }
}

// round 5
// speedup vs baseline: 1.7422x; 1.0450x over previous
#include <cuda_runtime.h>
#include <math.h>

#define L_   12
#define S_   512
#define B_   4
#define DIN_ 768
#define D_   1024
#define H_   16
#define F_   4096
#define HD_  64
#define T_   (S_*B_)   // 2048 tokens

// ---------------- scratch (static device globals; no runtime allocation) ----
__device__ float g_h[T_*D_];
__device__ float g_q[T_*D_];
__device__ float g_k[T_*D_];
__device__ float g_v[T_*D_];
__device__ float g_attn[T_*D_];
__device__ float g_ff[(size_t)T_*F_];
__device__ float g_scores[(size_t)B_*H_*S_*S_];   // 67 MB

// ---------------- tf32 helpers ---------------------------------------------
__device__ __forceinline__ unsigned f2tf32(float f) {
    unsigned u;
    asm("cvt.rna.tf32.f32 %0, %1;" : "=r"(u) : "f"(f));
    return u;
}

__device__ __forceinline__ void mma_tf32(float c[4],
    unsigned a0, unsigned a1, unsigned a2, unsigned a3,
    unsigned b0, unsigned b1)
{
    asm volatile(
        "mma.sync.aligned.m16n8k8.row.col.f32.tf32.tf32.f32 "
        "{%0,%1,%2,%3}, {%4,%5,%6,%7}, {%8,%9}, {%0,%1,%2,%3};"
        : "+f"(c[0]), "+f"(c[1]), "+f"(c[2]), "+f"(c[3])
        : "r"(a0), "r"(a1), "r"(a2), "r"(a3), "r"(b0), "r"(b1));
}

__device__ __forceinline__ void split_tf32(float f, float& hi, float& lo) {
    unsigned h = f2tf32(f);
    hi = __uint_as_float(h);
    lo = __uint_as_float(f2tf32(f - hi));
}

// ---------------- tensor-core GEMM (3xTF32, double-buffered smem) ----------
// C = A[MxK] @ W[KxN] + bias[c] + bias2[c] + rowvec[r]*colvec[c];
// optional exact GELU; + residual[r,c]
// block tile 128x128x32, 8 warps (2x4), warp tile 64x32, m16n8k8
// smem per stage: Ah/Al [128][36], Bh/Bl [32][136]; two stages ping-pong
#define TBM 128
#define TBN 128
#define TBK 32
#define A_STRIDE 36
#define B_STRIDE 136
#define OFF_AL  (TBM*A_STRIDE)                    // 4608
#define OFF_BH  (2*TBM*A_STRIDE)                  // 9216
#define OFF_BL  (2*TBM*A_STRIDE + TBK*B_STRIDE)   // 13568
#define STAGE_FLOATS (2*TBM*A_STRIDE + 2*TBK*B_STRIDE)   // 17920
#define SMEM_BYTES  (2*STAGE_FLOATS*4)            // 143360

__device__ __forceinline__ void store_split_tile(
    float* stage, int tid, const float4* pa, const float4* pb)
{
    #pragma unroll
    for (int it = 0; it < 4; it++) {
        const int s = tid + it * 256;
        const int ar = s >> 3, ac = (s & 7) * 4;
        float4 h4, l4;
        split_tf32(pa[it].x, h4.x, l4.x); split_tf32(pa[it].y, h4.y, l4.y);
        split_tf32(pa[it].z, h4.z, l4.z); split_tf32(pa[it].w, h4.w, l4.w);
        *(float4*)&stage[ar * A_STRIDE + ac] = h4;
        *(float4*)&stage[OFF_AL + ar * A_STRIDE + ac] = l4;
        const int br = s >> 5, bc = (s & 31) * 4;
        split_tf32(pb[it].x, h4.x, l4.x); split_tf32(pb[it].y, h4.y, l4.y);
        split_tf32(pb[it].z, h4.z, l4.z); split_tf32(pb[it].w, h4.w, l4.w);
        *(float4*)&stage[OFF_BH + br * B_STRIDE + bc] = h4;
        *(float4*)&stage[OFF_BL + br * B_STRIDE + bc] = l4;
    }
}

__global__ __launch_bounds__(256, 1) void gemm_tc(
    const float* __restrict__ A, const float* __restrict__ Bw,
    const float* __restrict__ bias, const float* __restrict__ bias2,
    const float* __restrict__ rowvec, const float* __restrict__ colvec,
    const float* __restrict__ residual,
    float* __restrict__ C, int M, int N, int K, int gelu_flag)
{
    extern __shared__ float smbuf[];
    float* cur = smbuf;
    float* nxt = smbuf + STAGE_FLOATS;

    const int tid  = threadIdx.x;
    const int warp = tid >> 5;
    const int lane = tid & 31;
    const int g    = lane >> 2;      // 0..7
    const int tig  = lane & 3;       // 0..3
    const int wm   = (warp >> 2) * 64;   // 0 or 64
    const int wn   = (warp & 3) * 32;    // 0,32,64,96

    const int row0 = blockIdx.y * TBM;
    const int col0 = blockIdx.x * TBN;

    float acc[4][4][4];
    #pragma unroll
    for (int mt = 0; mt < 4; mt++)
        #pragma unroll
        for (int nt = 0; nt < 4; nt++)
            #pragma unroll
            for (int r = 0; r < 4; r++) acc[mt][nt][r] = 0.f;

    float4 pa[4], pb[4];

    // ---- prologue: load tile 0 and split into cur
    #pragma unroll
    for (int it = 0; it < 4; it++) {
        const int s = tid + it * 256;
        pa[it] = *(const float4*)(A + (size_t)(row0 + (s >> 3)) * K + (s & 7) * 4);
        pb[it] = *(const float4*)(Bw + (size_t)(s >> 5) * N + col0 + (s & 31) * 4);
    }
    store_split_tile(cur, tid, pa, pb);
    __syncthreads();

    const int nk = K / TBK;
    for (int ki = 0; ki < nk; ki++) {
        // ---- prefetch next tile into registers
        const bool more = (ki + 1 < nk);
        if (more) {
            const int k0n = (ki + 1) * TBK;
            #pragma unroll
            for (int it = 0; it < 4; it++) {
                const int s = tid + it * 256;
                pa[it] = *(const float4*)(A + (size_t)(row0 + (s >> 3)) * K + k0n + (s & 7) * 4);
                pb[it] = *(const float4*)(Bw + (size_t)(k0n + (s >> 5)) * N + col0 + (s & 31) * 4);
            }
        }

        // ---- compute current stage (pure LDS + MMA)
        const float* Ah = cur;
        const float* Al = cur + OFF_AL;
        const float* Bh = cur + OFF_BH;
        const float* Bl = cur + OFF_BL;
        #pragma unroll
        for (int kk = 0; kk < TBK; kk += 8) {
            unsigned ah[4][4], al[4][4];
            #pragma unroll
            for (int mt = 0; mt < 4; mt++) {
                const int m = wm + mt * 16;
                const int r0i = (m + g) * A_STRIDE + kk + tig;
                const int r1i = (m + g + 8) * A_STRIDE + kk + tig;
                ah[mt][0] = __float_as_uint(Ah[r0i]);
                ah[mt][1] = __float_as_uint(Ah[r1i]);
                ah[mt][2] = __float_as_uint(Ah[r0i + 4]);
                ah[mt][3] = __float_as_uint(Ah[r1i + 4]);
                al[mt][0] = __float_as_uint(Al[r0i]);
                al[mt][1] = __float_as_uint(Al[r1i]);
                al[mt][2] = __float_as_uint(Al[r0i + 4]);
                al[mt][3] = __float_as_uint(Al[r1i + 4]);
            }
            unsigned bh[4][2], bl[4][2];
            #pragma unroll
            for (int nt = 0; nt < 4; nt++) {
                const int n = wn + nt * 8 + g;
                const int c0i = (kk + tig) * B_STRIDE + n;
                const int c1i = (kk + tig + 4) * B_STRIDE + n;
                bh[nt][0] = __float_as_uint(Bh[c0i]);
                bh[nt][1] = __float_as_uint(Bh[c1i]);
                bl[nt][0] = __float_as_uint(Bl[c0i]);
                bl[nt][1] = __float_as_uint(Bl[c1i]);
            }
            #pragma unroll
            for (int mt = 0; mt < 4; mt++)
                #pragma unroll
                for (int nt = 0; nt < 4; nt++) {
                    mma_tf32(acc[mt][nt], ah[mt][0], ah[mt][1], ah[mt][2], ah[mt][3],
                             bh[nt][0], bh[nt][1]);
                    mma_tf32(acc[mt][nt], al[mt][0], al[mt][1], al[mt][2], al[mt][3],
                             bh[nt][0], bh[nt][1]);
                    mma_tf32(acc[mt][nt], ah[mt][0], ah[mt][1], ah[mt][2], ah[mt][3],
                             bl[nt][0], bl[nt][1]);
                }
        }

        // ---- split-store prefetched tile into the OTHER stage, single sync
        if (more) store_split_tile(nxt, tid, pa, pb);
        __syncthreads();
        float* t = cur; cur = nxt; nxt = t;
    }

    // ---- epilogue
    #pragma unroll
    for (int mt = 0; mt < 4; mt++) {
        #pragma unroll
        for (int half = 0; half < 2; half++) {
            const int r = row0 + wm + mt * 16 + g + half * 8;
            const float rv = rowvec ? rowvec[r] : 0.f;
            #pragma unroll
            for (int nt = 0; nt < 4; nt++) {
                const int c = col0 + wn + nt * 8 + 2 * tig;
                float v0 = acc[mt][nt][half * 2 + 0];
                float v1 = acc[mt][nt][half * 2 + 1];
                if (bias)  { v0 += bias[c];  v1 += bias[c + 1]; }
                if (bias2) { v0 += bias2[c]; v1 += bias2[c + 1]; }
                if (rowvec) { v0 += rv * colvec[c]; v1 += rv * colvec[c + 1]; }
                if (gelu_flag) {
                    v0 = 0.5f * v0 * (1.f + erff(v0 * 0.70710678118654752f));
                    v1 = 0.5f * v1 * (1.f + erff(v1 * 0.70710678118654752f));
                }
                if (residual) {
                    float2 rr = *(const float2*)(residual + (size_t)r * N + c);
                    v0 += rr.x; v1 += rr.y;
                }
                float2 o; o.x = v0; o.y = v1;
                *(float2*)(C + (size_t)r * N + c) = o;
            }
        }
    }
}

// ---------------- LayerNorm: one block per token ---------------------------
__global__ __launch_bounds__(256) void ln_kernel(
    const float* __restrict__ x, const float* __restrict__ g,
    const float* __restrict__ bta, float* __restrict__ out)
{
    const int t = blockIdx.x;
    const int tid = threadIdx.x;
    const float* xr = x + (size_t)t * D_;

    float v[4];
    float s = 0.f, s2 = 0.f;
    #pragma unroll
    for (int i = 0; i < 4; i++) {
        v[i] = xr[tid + i*256];
        s  += v[i];
        s2 += v[i] * v[i];
    }
    #pragma unroll
    for (int o = 16; o; o >>= 1) {
        s  += __shfl_xor_sync(0xffffffffu, s,  o);
        s2 += __shfl_xor_sync(0xffffffffu, s2, o);
    }
    __shared__ float ss[8], ss2[8];
    if ((tid & 31) == 0) { ss[tid >> 5] = s; ss2[tid >> 5] = s2; }
    __syncthreads();
    s = 0.f; s2 = 0.f;
    #pragma unroll
    for (int w = 0; w < 8; w++) { s += ss[w]; s2 += ss2[w]; }

    const float mean = s * (1.f / D_);
    const float var  = s2 * (1.f / D_) - mean * mean;
    const float inv  = rsqrtf(var + 1e-5f);

    float* orow = out + (size_t)t * D_;
    #pragma unroll
    for (int i = 0; i < 4; i++) {
        const int c = tid + i*256;
        orow[c] = (v[i] - mean) * inv * g[c] + bta[c];
    }
}

// ---------------- RoPE (in-place, one thread owns the rotation pair) -------
__global__ __launch_bounds__(256) void rope_kernel(float* __restrict__ x)
{
    const int idx = blockIdx.x * 256 + threadIdx.x;   // T_*H_*32 = 1,048,576
    const int j = idx & 31;
    const int h = (idx >> 5) & 15;
    const int t = idx >> 9;                            // token 0..2047
    const int s = t >> 2;                              // sequence position (/B_)

    const float inv_freq = powf(10000.f, -((float)(2*j)) * (1.f / HD_));
    float sn, c;
    sincosf((float)s * inv_freq, &sn, &c);

    float* base = x + (size_t)t * D_ + h * HD_;
    const float x1 = base[j];
    const float x2 = base[j + 32];
    base[j]      = x1 * c - x2 * sn;
    base[j + 32] = x2 * c + x1 * sn;
}

// ---------------- scores = scale * Q K^T, masked ---------------------------
// grid (S/64, S/64, B*H), block 256; per-thread 4x4 output
__global__ __launch_bounds__(256) void qk_kernel(
    const float* __restrict__ q, const float* __restrict__ k,
    const int* __restrict__ mask, float* __restrict__ scores)
{
    const int bh = blockIdx.z;
    const int b = bh >> 4;
    const int h = bh & 15;
    const int qt = blockIdx.y * 64;
    const int kt = blockIdx.x * 64;

    __shared__ float Qs[HD_][65];
    __shared__ float Ks[HD_][65];

    const int tid = threadIdx.x;
    const int ty = tid >> 4, tx = tid & 15;
    const int lr = tid >> 4;
    const int lc = (tid & 15) * 4;

    #pragma unroll
    for (int it = 0; it < 4; it++) {
        const int m = lr + it*16;
        float4 a = *(const float4*)(q + ((size_t)(qt + m) * B_ + b) * D_ + h*HD_ + lc);
        Qs[lc+0][m]=a.x; Qs[lc+1][m]=a.y; Qs[lc+2][m]=a.z; Qs[lc+3][m]=a.w;
        float4 bb = *(const float4*)(k + ((size_t)(kt + m) * B_ + b) * D_ + h*HD_ + lc);
        Ks[lc+0][m]=bb.x; Ks[lc+1][m]=bb.y; Ks[lc+2][m]=bb.z; Ks[lc+3][m]=bb.w;
    }
    __syncthreads();

    float acc[4][4];
    #pragma unroll
    for (int i = 0; i < 4; i++)
        #pragma unroll
        for (int j = 0; j < 4; j++) acc[i][j] = 0.f;

    #pragma unroll
    for (int kk = 0; kk < HD_; kk++) {
        float av[4], bv[4];
        #pragma unroll
        for (int i = 0; i < 4; i++) av[i] = Qs[kk][ty*4 + i];
        #pragma unroll
        for (int j = 0; j < 4; j++) bv[j] = Ks[kk][tx*4 + j];
        #pragma unroll
        for (int i = 0; i < 4; i++)
            #pragma unroll
            for (int j = 0; j < 4; j++)
                acc[i][j] = fmaf(av[i], bv[j], acc[i][j]);
    }

    const float scale = 0.125f;  // 1/sqrt(64)
    #pragma unroll
    for (int i = 0; i < 4; i++) {
        const int qpos = qt + ty*4 + i;
        float* out = scores + ((size_t)bh * S_ + qpos) * S_;
        #pragma unroll
        for (int j = 0; j < 4; j++) {
            const int kpos = kt + tx*4 + j;
            float vsc = acc[i][j] * scale;
            if (mask[b * S_ + kpos] != 0) vsc = -1e30f;
            out[kpos] = vsc;
        }
    }
}

// ---------------- row softmax over 512 keys --------------------------------
__global__ __launch_bounds__(128) void softmax_kernel(float* __restrict__ scores)
{
    const size_t row = blockIdx.x;
    float* p = scores + row * S_;
    const int tid = threadIdx.x;

    float vals[4];
    float m = -3.0e38f;
    #pragma unroll
    for (int i = 0; i < 4; i++) { vals[i] = p[tid + i*128]; m = fmaxf(m, vals[i]); }
    #pragma unroll
    for (int o = 16; o; o >>= 1) m = fmaxf(m, __shfl_xor_sync(0xffffffffu, m, o));
    __shared__ float sm[4], ssum[4];
    if ((tid & 31) == 0) sm[tid >> 5] = m;
    __syncthreads();
    m = fmaxf(fmaxf(sm[0], sm[1]), fmaxf(sm[2], sm[3]));

    float s = 0.f;
    #pragma unroll
    for (int i = 0; i < 4; i++) { vals[i] = __expf(vals[i] - m); s += vals[i]; }
    #pragma unroll
    for (int o = 16; o; o >>= 1) s += __shfl_xor_sync(0xffffffffu, s, o);
    if ((tid & 31) == 0) ssum[tid >> 5] = s;
    __syncthreads();
    const float inv = 1.f / (ssum[0] + ssum[1] + ssum[2] + ssum[3]);

    #pragma unroll
    for (int i = 0; i < 4; i++) p[tid + i*128] = vals[i] * inv;
}

// ---------------- attn = probs @ V, scattered to [t, d] layout -------------
// grid (1, S/64, B*H), block 256
__global__ __launch_bounds__(256) void pv_kernel(
    const float* __restrict__ scores, const float* __restrict__ v,
    float* __restrict__ attn)
{
    const int bh = blockIdx.z;
    const int b = bh >> 4, h = bh & 15;
    const int qt = blockIdx.y * 64;

    __shared__ float Ps[32][65];
    __shared__ float Vs[32][64];

    const int tid = threadIdx.x;
    const int ty = tid >> 4, tx = tid & 15;
    const int pr = tid >> 3;           // 0..31
    const int pc = (tid & 7) * 4;      // 0..28
    const int vr = tid >> 4;           // 0..15
    const int vc = (tid & 15) * 4;     // 0..60

    float acc[4][4];
    #pragma unroll
    for (int i = 0; i < 4; i++)
        #pragma unroll
        for (int j = 0; j < 4; j++) acc[i][j] = 0.f;

    for (int kt = 0; kt < S_; kt += 32) {
        #pragma unroll
        for (int it = 0; it < 2; it++) {
            const int m = pr + it*32;   // q row 0..63
            float4 a = *(const float4*)(scores + ((size_t)bh*S_ + qt + m)*S_ + kt + pc);
            Ps[pc+0][m]=a.x; Ps[pc+1][m]=a.y; Ps[pc+2][m]=a.z; Ps[pc+3][m]=a.w;
        }
        #pragma unroll
        for (int it = 0; it < 2; it++) {
            const int kr = vr + it*16;  // k row 0..31
            float4 bb = *(const float4*)(v + ((size_t)(kt + kr)*B_ + b)*D_ + h*HD_ + vc);
            *(float4*)&Vs[kr][vc] = bb;
        }
        __syncthreads();

        #pragma unroll
        for (int kk = 0; kk < 32; kk++) {
            float av[4], bv[4];
            #pragma unroll
            for (int i = 0; i < 4; i++) av[i] = Ps[kk][ty*4 + i];
            #pragma unroll
            for (int j = 0; j < 4; j++) bv[j] = Vs[kk][tx*4 + j];
            #pragma unroll
            for (int i = 0; i < 4; i++)
                #pragma unroll
                for (int j = 0; j < 4; j++)
                    acc[i][j] = fmaf(av[i], bv[j], acc[i][j]);
        }
        __syncthreads();
    }

    #pragma unroll
    for (int i = 0; i < 4; i++) {
        const int qpos = qt + ty*4 + i;
        float* orow = attn + ((size_t)qpos * B_ + b) * D_ + h*HD_;
        #pragma unroll
        for (int j = 0; j < 4; j++)
            orow[tx*4 + j] = acc[i][j];
    }
}

// ---------------- host orchestration ---------------------------------------
extern "C" void kernel_launch(void* const* d_in, const int* in_sizes, int n_in,
                              void* d_out, int out_size)
{
    (void)in_sizes; (void)n_in; (void)out_size;

    const float* segments  = (const float*)d_in[0];
    const float* durations = (const float*)d_in[1];
    const int*   padmask   = (const int*)d_in[2];   // bool promoted to int32
    const float* Wproj = (const float*)d_in[3];
    const float* bproj = (const float*)d_in[4];
    const float* Wdur  = (const float*)d_in[5];
    const float* bdur  = (const float*)d_in[6];
    const float* ln1_g = (const float*)d_in[7];
    const float* ln1_b = (const float*)d_in[8];
    const float* Wq = (const float*)d_in[9];
    const float* bq = (const float*)d_in[10];
    const float* Wk = (const float*)d_in[11];
    const float* bk = (const float*)d_in[12];
    const float* Wv = (const float*)d_in[13];
    const float* bv = (const float*)d_in[14];
    const float* Wo = (const float*)d_in[15];
    const float* bo = (const float*)d_in[16];
    const float* ln2_g = (const float*)d_in[17];
    const float* ln2_b = (const float*)d_in[18];
    const float* Wff1 = (const float*)d_in[19];
    const float* bff1 = (const float*)d_in[20];
    const float* Wff2 = (const float*)d_in[21];
    const float* bff2 = (const float*)d_in[22];

    float* x = (float*)d_out;   // residual stream lives in d_out

    float *h, *q, *k, *v, *attn, *ff, *scores;
    cudaGetSymbolAddress((void**)&h,      g_h);
    cudaGetSymbolAddress((void**)&q,      g_q);
    cudaGetSymbolAddress((void**)&k,      g_k);
    cudaGetSymbolAddress((void**)&v,      g_v);
    cudaGetSymbolAddress((void**)&attn,   g_attn);
    cudaGetSymbolAddress((void**)&ff,     g_ff);
    cudaGetSymbolAddress((void**)&scores, g_scores);

    cudaFuncSetAttribute(gemm_tc,
        cudaFuncAttributeMaxDynamicSharedMemorySize, SMEM_BYTES);

    const dim3 blk(256);

    // x = segments @ Wproj + bproj + durations*Wdur + bdur
    gemm_tc<<<dim3(D_/TBN, T_/TBM), blk, SMEM_BYTES>>>(
        segments, Wproj, bproj, bdur, durations, Wdur, nullptr,
        x, T_, D_, DIN_, 0);

    for (int l = 0; l < L_; l++) {
        const float* wq = Wq + (size_t)l*D_*D_;
        const float* wk = Wk + (size_t)l*D_*D_;
        const float* wv = Wv + (size_t)l*D_*D_;
        const float* wo = Wo + (size_t)l*D_*D_;
        const float* w1 = Wff1 + (size_t)l*D_*F_;
        const float* w2 = Wff2 + (size_t)l*F_*D_;

        ln_kernel<<<T_, 256>>>(x, ln1_g + l*D_, ln1_b + l*D_, h);

        gemm_tc<<<dim3(D_/TBN, T_/TBM), blk, SMEM_BYTES>>>(h, wq, bq + l*D_,
            nullptr, nullptr, nullptr, nullptr, q, T_, D_, D_, 0);
        gemm_tc<<<dim3(D_/TBN, T_/TBM), blk, SMEM_BYTES>>>(h, wk, bk + l*D_,
            nullptr, nullptr, nullptr, nullptr, k, T_, D_, D_, 0);
        gemm_tc<<<dim3(D_/TBN, T_/TBM), blk, SMEM_BYTES>>>(h, wv, bv + l*D_,
            nullptr, nullptr, nullptr, nullptr, v, T_, D_, D_, 0);

        rope_kernel<<<(T_*H_*32)/256, 256>>>(q);
        rope_kernel<<<(T_*H_*32)/256, 256>>>(k);

        qk_kernel<<<dim3(S_/64, S_/64, B_*H_), blk>>>(q, k, padmask, scores);
        softmax_kernel<<<B_*H_*S_, 128>>>(scores);
        pv_kernel<<<dim3(1, S_/64, B_*H_), blk>>>(scores, v, attn);

        // x = x + attn @ Wo + bo
        gemm_tc<<<dim3(D_/TBN, T_/TBM), blk, SMEM_BYTES>>>(attn, wo, bo + l*D_,
            nullptr, nullptr, nullptr, x, x, T_, D_, D_, 0);

        ln_kernel<<<T_, 256>>>(x, ln2_g + l*D_, ln2_b + l*D_, h);

        // ff = gelu(h @ W1 + b1)
        gemm_tc<<<dim3(F_/TBN, T_/TBM), blk, SMEM_BYTES>>>(h, w1, bff1 + l*F_,
            nullptr, nullptr, nullptr, nullptr, ff, T_, F_, D_, 1);

        // x = x + ff @ W2 + b2
        gemm_tc<<<dim3(D_/TBN, T_/TBM), blk, SMEM_BYTES>>>(ff, w2, bff2 + l*D_,
            nullptr, nullptr, nullptr, x, x, T_, D_, F_, 0);
    }
}